// round 2
// baseline (speedup 1.0000x reference)
#include <cuda_runtime.h>
#include <cstdint>

// ============================================================================
// BCQLinear: y = (x[:, in_reorder] @ dequant(qweight))[:, out_reorder]
// M=128, K=N=4096, WBITS=3, GS=OFI=128.
// compute_100-safe path (no tcgen05/TMA): legacy mma.sync m16n8k8 tf32 with
// RNA rounding, register-fused 3-bit dequant, K-split=4, deterministic.
// ============================================================================

#define M_TOK   128
#define IN_F    4096
#define OUT_F   4096
#define NGRP    32
#define KSPLIT  4
#define GPS     8            // groups per K-split

// Scratch (static __device__ — no allocations)
// x pre-permuted + tf32-rounded, stored in exact A-fragment order:
//   [g][kstep 16][mtile 8][lane 32][reg 4]
__device__ float g_x_frag[NGRP * 16 * 8 * 32 * 4];     // 2 MB
__device__ float g_t_part[KSPLIT * M_TOK * OUT_F];     // 8 MB K-split partials

__device__ __forceinline__ uint32_t f2tf32(float f) {
    // round-to-nearest tf32 — truncation would bias every dot product low
    uint32_t u;
    asm("cvt.rna.tf32.f32 %0, %1;" : "=r"(u) : "f"(f));
    return u;
}

// ---------------------------------------------------------------------------
// Kernel 1: gather x[:, in_reorder], tf32-round, write A-fragment layout.
// Write index is the thread index (perfectly coalesced stores); the read is a
// gather from the 2MB L2-resident x.
// Fragment map (mma.m16n8k8.tf32 A, row.col):
//   lane = (mrow&7)*4 + (kcol&3);  reg = (mrow>>3) | ((kcol>>2)<<1)
// ---------------------------------------------------------------------------
__global__ __launch_bounds__(256)
void prep_x_kernel(const float* __restrict__ x, const int* __restrict__ in_reorder) {
    const int idx  = blockIdx.x * 256 + threadIdx.x;        // 524288 total
    const int r    = idx & 3;
    const int lane = (idx >> 2) & 31;
    const int mt   = (idx >> 7) & 7;
    const int ks   = (idx >> 10) & 15;
    const int g    = (idx >> 14) & 31;
    const int mrow = (lane >> 2) | ((r & 1) << 3);
    const int kcol = (lane & 3) | ((r & 2) << 1);
    const int m = mt * 16 + mrow;
    const int k = g * 128 + ks * 8 + kcol;
    const float v = x[m * IN_F + __ldg(&in_reorder[k])];
    g_x_frag[idx] = __uint_as_float(f2tf32(v));
}

// ---------------------------------------------------------------------------
// Kernel 2: fused 3-bit dequant + tf32 mma.sync GEMM.
// grid (32 out-blocks, 4 K-splits) = 128 CTAs, 256 threads (8 warps).
// Warp w: m-half = w&1 (64 rows), n-quarter = w>>2... = w>>1 (32 cols).
// Each CTA covers exactly one quant out-block (OFI=128) -> j = o>>5 = nq.
// ---------------------------------------------------------------------------
__global__ __launch_bounds__(256)
void bcq_gemm_kernel(const int* __restrict__ qweight,
                     const float* __restrict__ alpha,
                     const float* __restrict__ beta,
                     const int* __restrict__ offset)
{
    __shared__ int Qsm[1536];                 // one (group, out-block): 3 planes x 512
    const int tid  = threadIdx.x;
    const int lane = tid & 31;
    const int wid  = tid >> 5;
    const int nb = blockIdx.x, split = blockIdx.y;
    const int mh = wid & 1;                   // m-half (0..1)
    const int nq = wid >> 1;                  // n-quarter (0..3) == word sub-index j

    float acc[4][4][4];
    #pragma unroll
    for (int a = 0; a < 4; a++)
        #pragma unroll
        for (int b = 0; b < 4; b++)
            #pragma unroll
            for (int c = 0; c < 4; c++) acc[a][b][c] = 0.f;

    // --- prefetch group 0 (registers) ---
    int   qn[6];
    float an[4], bn[4];
    {
        const int g0 = split * GPS;
        const int* src = qweight + __ldg(&offset[g0 * 32 + nb]);
        #pragma unroll
        for (int u = 0; u < 6; u++) qn[u] = __ldg(src + tid + u * 256);
        #pragma unroll
        for (int nt = 0; nt < 4; nt++) {
            const int o = nq * 32 + nt * 8 + (lane >> 2);
            an[nt] = __ldg(&alpha[g0 * OUT_F + nb * 128 + o]);
            bn[nt] = __ldg(&beta [g0 * OUT_F + nb * 128 + o]);
        }
    }

    for (int gi = 0; gi < GPS; gi++) {
        const int g = split * GPS + gi;

        // w = q*a + b with q = 2v-7  ->  w = v*(2a) + (b - 7a)
        float c1[4], c0[4];
        #pragma unroll
        for (int nt = 0; nt < 4; nt++) {
            c1[nt] = 2.f * an[nt];
            c0[nt] = fmaf(-7.f, an[nt], bn[nt]);
        }

        __syncthreads();                       // Qsm free from previous group
        #pragma unroll
        for (int u = 0; u < 6; u++) Qsm[tid + u * 256] = qn[u];
        __syncthreads();                       // Qsm visible

        // prefetch next group while computing this one
        if (gi + 1 < GPS) {
            const int gnx = g + 1;
            const int* src = qweight + __ldg(&offset[gnx * 32 + nb]);
            #pragma unroll
            for (int u = 0; u < 6; u++) qn[u] = __ldg(src + tid + u * 256);
            #pragma unroll
            for (int nt = 0; nt < 4; nt++) {
                const int o = nq * 32 + nt * 8 + (lane >> 2);
                an[nt] = __ldg(&alpha[gnx * OUT_F + nb * 128 + o]);
                bn[nt] = __ldg(&beta [gnx * OUT_F + nb * 128 + o]);
            }
        }

        const float4* Abase =
            ((const float4*)g_x_frag) + (size_t)g * (16 * 8 * 32) + lane;

        #pragma unroll 4
        for (int ks = 0; ks < 16; ks++) {
            // --- A fragments: one coalesced LDG.128 per m-tile ---
            uint32_t A[4][4];
            #pragma unroll
            for (int mt = 0; mt < 4; mt++) {
                const float4 t = Abase[(ks * 8 + mh * 4 + mt) * 32];
                A[mt][0] = __float_as_uint(t.x);
                A[mt][1] = __float_as_uint(t.y);
                A[mt][2] = __float_as_uint(t.z);
                A[mt][3] = __float_as_uint(t.w);
            }

            // --- qweight words (broadcast LDS: 4 distinct addrs per warp) ---
            const int i0 = ks * 8 + (lane & 3);
            const uint32_t q0l = (uint32_t)Qsm[       i0      * 4 + nq];
            const uint32_t q0h = (uint32_t)Qsm[      (i0 + 4) * 4 + nq];
            const uint32_t q1l = (uint32_t)Qsm[512  + i0      * 4 + nq];
            const uint32_t q1h = (uint32_t)Qsm[512  + (i0 + 4) * 4 + nq];
            const uint32_t q2l = (uint32_t)Qsm[1024 + i0      * 4 + nq];
            const uint32_t q2h = (uint32_t)Qsm[1024 + (i0 + 4) * 4 + nq];

            // --- dequant directly into B fragments ---
            uint32_t B[4][2];
            #pragma unroll
            for (int nt = 0; nt < 4; nt++) {
                const int sh = nt * 8 + (lane >> 2);      // bit position = o & 31
                const int vl = (int)(((q0l >> sh) & 1u)
                                   | (((q1l >> sh) & 1u) << 1)
                                   | (((q2l >> sh) & 1u) << 2));
                const int vh = (int)(((q0h >> sh) & 1u)
                                   | (((q1h >> sh) & 1u) << 1)
                                   | (((q2h >> sh) & 1u) << 2));
                B[nt][0] = f2tf32(fmaf((float)vl, c1[nt], c0[nt]));
                B[nt][1] = f2tf32(fmaf((float)vh, c1[nt], c0[nt]));
            }

            // --- 16 mma.sync per warp per k-step ---
            #pragma unroll
            for (int mt = 0; mt < 4; mt++)
                #pragma unroll
                for (int nt = 0; nt < 4; nt++)
                    asm volatile(
                        "mma.sync.aligned.m16n8k8.row.col.f32.tf32.tf32.f32 "
                        "{%0,%1,%2,%3}, {%4,%5,%6,%7}, {%8,%9}, {%0,%1,%2,%3};"
                        : "+f"(acc[mt][nt][0]), "+f"(acc[mt][nt][1]),
                          "+f"(acc[mt][nt][2]), "+f"(acc[mt][nt][3])
                        : "r"(A[mt][0]), "r"(A[mt][1]), "r"(A[mt][2]), "r"(A[mt][3]),
                          "r"(B[nt][0]), "r"(B[nt][1]));
        }
    }

    // --- epilogue: write K-split partials (deterministic, no atomics) ---
    float* dst = g_t_part + (size_t)split * (M_TOK * OUT_F);
    #pragma unroll
    for (int mt = 0; mt < 4; mt++) {
        const int row0 = mh * 64 + mt * 16 + (lane >> 2);
        #pragma unroll
        for (int nt = 0; nt < 4; nt++) {
            const int col = nb * 128 + nq * 32 + nt * 8 + (lane & 3) * 2;
            *(float2*)&dst[ row0      * OUT_F + col] =
                make_float2(acc[mt][nt][0], acc[mt][nt][1]);
            *(float2*)&dst[(row0 + 8) * OUT_F + col] =
                make_float2(acc[mt][nt][2], acc[mt][nt][3]);
        }
    }
}

// ---------------------------------------------------------------------------
// Kernel 3: reduce 4 K-splits + output permutation
// ---------------------------------------------------------------------------
__global__ __launch_bounds__(256)
void finalize_kernel(const int* __restrict__ out_reorder, float* __restrict__ y) {
    const int idx = blockIdx.x * 256 + threadIdx.x;     // 524288 total
    const int m = idx >> 12;
    const int c = idx & (OUT_F - 1);
    const int n = __ldg(&out_reorder[c]);
    const size_t p = (size_t)m * OUT_F + n;
    const size_t S = (size_t)M_TOK * OUT_F;
    y[idx] = g_t_part[p] + g_t_part[S + p] + g_t_part[2 * S + p] + g_t_part[3 * S + p];
}

// ---------------------------------------------------------------------------
// Launch
// ---------------------------------------------------------------------------
extern "C" void kernel_launch(void* const* d_in, const int* in_sizes, int n_in,
                              void* d_out, int out_size) {
    const float* x           = (const float*)d_in[0];
    const int*   qweight     = (const int*)  d_in[1];
    const float* alpha       = (const float*)d_in[2];
    const float* beta        = (const float*)d_in[3];
    // d_in[4] = block_bitwidth (uniform 3, unused)
    const int*   offset      = (const int*)  d_in[5];
    const int*   in_reorder  = (const int*)  d_in[6];
    const int*   out_reorder = (const int*)  d_in[7];
    float* y = (float*)d_out;

    prep_x_kernel<<<2048, 256>>>(x, in_reorder);
    bcq_gemm_kernel<<<dim3(32, KSPLIT), 256>>>(qweight, alpha, beta, offset);
    finalize_kernel<<<2048, 256>>>(out_reorder, y);
}